// round 15
// baseline (speedup 1.0000x reference)
#include <cuda_runtime.h>
#include <math.h>

// Shapes fixed by the reference problem.
#define B_DIM 32
#define T_DIM 8192
#define C_DIM 256
#define NSTAT 5                  // S1, S2, S3, S4, Sp
#define EPSF 1e-6

// Balanced decomposition: work quantum = 4 t-rows of full C (4KB).
#define NCTA 592                 // 4 * 148 SMs -> exactly 4 CTAs per SM
#define QTOT 65536               // B_DIM * T_DIM / 4
#define QPB  2048                // quanta per batch (T_DIM / 4)
#define QBASE 110                // QTOT / NCTA
#define QREM  416                // QTOT - QBASE*NCTA  (first QREM CTAs get +1)
#define QTHRESH 46176            // 111 * QREM

#define CG 64                    // c-groups (of 4 channels) per block
#define TLANES 4                 // t-lanes per block

// Partial sums: [NSTAT][NCTA][2 segments][C]  (~6.1 MB)
__device__ float g_scratch[NSTAT * NCTA * 2 * C_DIM];
// Completion counters, one per batch. Zero-initialized; reset by reducer.
__device__ int g_count[B_DIM];

// ---- packed f32x2 helpers --------------------------------------------------
__device__ __forceinline__ unsigned long long mul2(unsigned long long a,
                                                   unsigned long long b) {
    unsigned long long d;
    asm("mul.rn.f32x2 %0, %1, %2;" : "=l"(d) : "l"(a), "l"(b));
    return d;
}
__device__ __forceinline__ unsigned long long add2(unsigned long long a,
                                                   unsigned long long b) {
    unsigned long long d;
    asm("add.rn.f32x2 %0, %1, %2;" : "=l"(d) : "l"(a), "l"(b));
    return d;
}
__device__ __forceinline__ unsigned long long fma2(unsigned long long a,
                                                   unsigned long long b,
                                                   unsigned long long c) {
    unsigned long long d;
    asm("fma.rn.f32x2 %0, %1, %2, %3;" : "=l"(d) : "l"(a), "l"(b), "l"(c));
    return d;
}
__device__ __forceinline__ unsigned long long pack2(float lo, float hi) {
    unsigned long long r;
    asm("mov.b64 %0, {%1, %2};" : "=l"(r) : "f"(lo), "f"(hi));
    return r;
}
__device__ __forceinline__ void unpack2(unsigned long long v, float& lo, float& hi) {
    asm("mov.b64 {%0, %1}, %2;" : "=f"(lo), "=f"(hi) : "l"(v));
}
// ----------------------------------------------------------------------------

// First CTA index whose quantum range contains quantum q (inverse of q0(j)).
__device__ __forceinline__ int inv_cta(int q) {
    return (q < QTHRESH) ? (q / (QBASE + 1)) : ((q - QREM) / QBASE);
}
__device__ __forceinline__ int q_start(int j) {
    return j * QBASE + min(j, QREM);
}

__global__ __launch_bounds__(256, 4)
void hom_fused(const float* __restrict__ x, const float* __restrict__ p,
               float* __restrict__ out)
{
    const int j     = blockIdx.x;
    const int tid   = threadIdx.x;
    const int cg    = tid & 63;      // 0..63 channel group
    const int tlane = tid >> 6;      // 0..3

    const float pv = p[0];
    const bool p_is_one = (pv == 1.0f);

    // This CTA's quantum range [q0, qe), split into <=2 same-batch segments.
    const int q0  = q_start(j);
    const int cnt = QBASE + (j < QREM);
    const int qe  = q0 + cnt;
    const int b0  = q0 / QPB;
    const int qb  = (b0 + 1) * QPB;          // end of batch b0 in quanta
    const int c0  = min(qe, qb) - q0;        // seg0 length (>=1)
    const int c1  = qe - min(qe, qb);        // seg1 length (may be 0)

    __shared__ float sm[TLANES][CG][NSTAT * 4];
    __shared__ int is_last;

    const size_t step = (size_t)TLANES * C_DIM;   // 4 t-rows (in floats)

    #pragma unroll 1
    for (int seg = 0; seg < 2; ++seg) {
        const int segCnt = (seg == 0) ? c0 : c1;
        if (segCnt == 0) continue;           // uniform across block
        const int qs = (seg == 0) ? q0 : qb;
        const int bb = b0 + seg;

        // base: x[bb, (qs%QPB)*4 + tlane, cg*4]
        const int t0 = (qs - bb * QPB) * 4 + tlane;
        const float* ptr = x + ((size_t)bb * T_DIM + t0) * C_DIM + cg * 4;

        unsigned long long s1xy = 0ull, s1zw = 0ull;
        unsigned long long s2xy = 0ull, s2zw = 0ull;
        unsigned long long s3xy = 0ull, s3zw = 0ull;
        unsigned long long s4xy = 0ull, s4zw = 0ull;
        unsigned long long spxy = 0ull, spzw = 0ull;

        if (p_is_one) {
            #pragma unroll 8
            for (int i = 0; i < segCnt; ++i) {
                const ulonglong2 v = *reinterpret_cast<const ulonglong2*>(
                    ptr + (size_t)i * step);
                const unsigned long long vxy = v.x, vzw = v.y;
                const unsigned long long x2xy = mul2(vxy, vxy);
                const unsigned long long x2zw = mul2(vzw, vzw);
                s1xy = add2(s1xy, vxy);          s1zw = add2(s1zw, vzw);
                s2xy = add2(s2xy, x2xy);         s2zw = add2(s2zw, x2zw);
                s3xy = fma2(x2xy, vxy, s3xy);    s3zw = fma2(x2zw, vzw, s3zw);
                s4xy = fma2(x2xy, x2xy, s4xy);   s4zw = fma2(x2zw, x2zw, s4zw);
            }
            spxy = s1xy; spzw = s1zw;   // mean(x^1) == mean(x)
        } else {
            #pragma unroll 4
            for (int i = 0; i < segCnt; ++i) {
                const ulonglong2 v = *reinterpret_cast<const ulonglong2*>(
                    ptr + (size_t)i * step);
                const unsigned long long vxy = v.x, vzw = v.y;
                const unsigned long long x2xy = mul2(vxy, vxy);
                const unsigned long long x2zw = mul2(vzw, vzw);
                s1xy = add2(s1xy, vxy);          s1zw = add2(s1zw, vzw);
                s2xy = add2(s2xy, x2xy);         s2zw = add2(s2zw, x2zw);
                s3xy = fma2(x2xy, vxy, s3xy);    s3zw = fma2(x2zw, vzw, s3zw);
                s4xy = fma2(x2xy, x2xy, s4xy);   s4zw = fma2(x2zw, x2zw, s4zw);
                float ax, ay, az, aw;
                unpack2(vxy, ax, ay);
                unpack2(vzw, az, aw);
                spxy = add2(spxy, pack2(__powf(ax, pv), __powf(ay, pv)));
                spzw = add2(spzw, pack2(__powf(az, pv), __powf(aw, pv)));
            }
        }

        // Stage per-thread sums in shared: sm[tlane][cg][stat*4+sub]
        {
            float* dst = sm[tlane][cg];
            unpack2(s1xy, dst[ 0], dst[ 1]); unpack2(s1zw, dst[ 2], dst[ 3]);
            unpack2(s2xy, dst[ 4], dst[ 5]); unpack2(s2zw, dst[ 6], dst[ 7]);
            unpack2(s3xy, dst[ 8], dst[ 9]); unpack2(s3zw, dst[10], dst[11]);
            unpack2(s4xy, dst[12], dst[13]); unpack2(s4zw, dst[14], dst[15]);
            unpack2(spxy, dst[16], dst[17]); unpack2(spzw, dst[18], dst[19]);
        }
        __syncthreads();

        // Thread tid owns channel c = tid: reduce 4 t-lanes, write slot (j, seg).
        {
            const int c   = tid;
            const int cgq = c >> 2;
            const int sub = c & 3;
            #pragma unroll
            for (int stat = 0; stat < NSTAT; ++stat) {
                const int jj = stat * 4 + sub;
                const float v = sm[0][cgq][jj] + sm[1][cgq][jj]
                              + sm[2][cgq][jj] + sm[3][cgq][jj];
                g_scratch[((size_t)(stat * NCTA + j) * 2 + seg) * C_DIM + c] = v;
            }
        }

        // ---- last-CTA-done final reduction for batch bb ----
        __threadfence();          // publish this CTA's partials
        __syncthreads();          // all writes done; also guards sm reuse
        if (tid == 0) {
            const int jF = inv_cta(bb * QPB);
            const int jL = inv_cta(bb * QPB + QPB - 1);
            const int nPart = jL - jF + 1;
            const int old = atomicAdd(&g_count[bb], 1);
            is_last = (old == nPart - 1);
        }
        __syncthreads();

        if (is_last) {
            __threadfence();      // acquire: see all participants' partials
            const int c = tid;    // one channel per thread
            const int jF = inv_cta(bb * QPB);
            const int jL = inv_cta(bb * QPB + QPB - 1);

            float S[NSTAT];
            #pragma unroll
            for (int s = 0; s < NSTAT; ++s) S[s] = 0.f;

            for (int jj = jF; jj <= jL; ++jj) {
                const int sj = ((q_start(jj) / QPB) == bb) ? 0 : 1;
                #pragma unroll
                for (int s = 0; s < NSTAT; ++s) {
                    S[s] += g_scratch[((size_t)(s * NCTA + jj) * 2 + sj) * C_DIM + c];
                }
            }

            const double invT = 1.0 / (double)T_DIM;
            const double mu  = (double)S[0] * invT;
            const double m2r = (double)S[1] * invT;   // E[x^2]
            const double m3r = (double)S[2] * invT;   // E[x^3]
            const double m4r = (double)S[3] * invT;   // E[x^4]
            const double grp = (double)S[4] * invT;

            const double mu2 = mu * mu;
            const double var = m2r - mu2;
            const double m3  = m3r - 3.0 * mu * m2r + 2.0 * mu * mu2;
            const double m4  = m4r - 4.0 * mu * m3r + 6.0 * mu2 * m2r
                             - 3.0 * mu2 * mu2;

            const double ve   = var + (double)EPSF;
            const double std_ = sqrt(ve);
            const double skew = m3 / (ve * std_);   // std^3
            const double kurt = m4 / (ve * ve);     // std^4

            float* o = out + (size_t)bb * (4 * C_DIM);
            o[c]             = (float)grp;
            o[C_DIM + c]     = (float)var;
            o[2 * C_DIM + c] = (float)skew;
            o[3 * C_DIM + c] = (float)kurt;

            if (tid == 0) g_count[bb] = 0;   // reset for next graph replay
            __syncthreads();                  // keep block in step for seg loop
        }
    }
}

extern "C" void kernel_launch(void* const* d_in, const int* in_sizes, int n_in,
                              void* d_out, int out_size)
{
    const float* x = (const float*)d_in[0];
    const float* p = (const float*)d_in[1];
    float* out = (float*)d_out;

    hom_fused<<<NCTA, 256>>>(x, p, out);
}